// round 13
// baseline (speedup 1.0000x reference)
#include <cuda_runtime.h>
#include <cuda_fp16.h>
#include <cstdint>

#define V_NODES 50000
#define FEAT    512          // B * Cin
#define CIN     128
#define COUT    128
#define BATCH   4
#define MROWS   (V_NODES * BATCH)   // 200000
#define MAXE    800000
#define KORD    5
#define NB_SCAN ((V_NODES + 255) / 256)   // 196
#define NCHUNK  2                          // 2 x 256-feature slices

// ---------------- static device scratch (no allocations allowed) ----------------
__device__ __half g_h0[(size_t)V_NODES * FEAT];     // P0..P4 fp16
__device__ __half g_h1[(size_t)V_NODES * FEAT];
__device__ __half g_h2[(size_t)V_NODES * FEAT];
__device__ __half g_h3[(size_t)V_NODES * FEAT];
__device__ __half g_h4[(size_t)V_NODES * FEAT];
__device__ __half g_wh[KORD * CIN * COUT];          // combined weights fp16 (layout [k][o][i])
__device__ float  g_acc[(size_t)(MROWS + 128) * COUT];  // fp32 partial (padded vs tile overrun)
__device__ int    g_rp[V_NODES + 1];
__device__ int    g_cnt[V_NODES];
__device__ int    g_ccol[MAXE];
__device__ float  g_cval[MAXE];
// decoupled-lookback scan state (re-zeroed by wcomb_k every replay)
__device__ int    g_ticket;
__device__ int    g_state[NB_SCAN];   // 0 = none, 1 = aggregate ready, 2 = prefix ready
__device__ int    g_aggv[NB_SCAN];
__device__ int    g_inclv[NB_SCAN];

__device__ __forceinline__ __half* pick_h(int i) {
    switch (i) {
        case 0: return g_h0;
        case 1: return g_h1;
        case 2: return g_h2;
        case 3: return g_h3;
        default: return g_h4;
    }
}

// ---------------- fp16 mma ----------------
__device__ __forceinline__ void mma_f16(float* d, const uint32_t* a, const uint32_t* b) {
    asm volatile(
        "mma.sync.aligned.m16n8k16.row.col.f32.f16.f16.f32 "
        "{%0,%1,%2,%3}, {%4,%5,%6,%7}, {%8,%9}, {%0,%1,%2,%3};"
        : "+f"(d[0]), "+f"(d[1]), "+f"(d[2]), "+f"(d[3])
        : "r"(a[0]), "r"(a[1]), "r"(a[2]), "r"(a[3]), "r"(b[0]), "r"(b[1]));
}

// ---------------- cp.async helpers ----------------
__device__ __forceinline__ void cp_async16(void* smem_dst, const void* gmem_src) {
    uint32_t s = (uint32_t)__cvta_generic_to_shared(smem_dst);
    asm volatile("cp.async.cg.shared.global [%0], [%1], 16;" :: "r"(s), "l"(gmem_src));
}
__device__ __forceinline__ void cp_commit() {
    asm volatile("cp.async.commit_group;");
}
template <int N>
__device__ __forceinline__ void cp_wait() {
    asm volatile("cp.async.wait_group %0;" :: "n"(N));
}

// ---------------- transpose: x (512, V) -> g_h0 (V, 512) fp16 ----------------
__global__ void transpose_in(const float* __restrict__ x) {
    __shared__ float tile[32][33];
    int v = blockIdx.x * 32 + threadIdx.x;
    int f = blockIdx.y * 32 + threadIdx.y;
    if (v < V_NODES)
        tile[threadIdx.y][threadIdx.x] = x[(size_t)f * V_NODES + v];
    __syncthreads();
    int vo = blockIdx.x * 32 + threadIdx.y;
    int fo = blockIdx.y * 32 + threadIdx.x;
    if (vo < V_NODES)
        g_h0[(size_t)vo * FEAT + fo] = __float2half(tile[threadIdx.x][threadIdx.y]);
}

// ---------------- combined weights (fp16, [k][o][i]) + zero scan state + g_cnt ----
// T0..T4 = {P0, P1, 2P2-P0, 4P3-3P1, 8P4-8P2+P0};  out = sum_k Tk Wk = sum_j Pj W~j
__global__ void wcomb_k(const float* __restrict__ w) {
    int gid = blockIdx.x * 256 + threadIdx.x;
    if (gid < V_NODES) g_cnt[gid] = 0;
    if (gid < NB_SCAN) g_state[gid] = 0;
    if (gid == 0) g_ticket = 0;
    if (gid >= CIN * COUT) return;
    const int S = CIN * COUT;
    float w0 = w[gid], w1 = w[gid + S], w2 = w[gid + 2 * S], w3 = w[gid + 3 * S], w4 = w[gid + 4 * S];
    float wt[KORD];
    wt[0] = w0 - w2 + w4;
    wt[1] = w1 - 3.f * w3;
    wt[2] = 2.f * w2 - 8.f * w4;
    wt[3] = 4.f * w3;
    wt[4] = 8.f * w4;
    int iin = gid >> 7, o = gid & 127;
#pragma unroll
    for (int j = 0; j < KORD; j++)
        g_wh[j * S + o * 128 + iin] = __float2half(wt[j]);
}

// ---------------- CSR build ----------------
__global__ void count_k(const int* __restrict__ rows, int E) {
    int e = blockIdx.x * blockDim.x + threadIdx.x;
    int stride = gridDim.x * blockDim.x;
    for (; e < E; e += stride) atomicAdd(&g_cnt[rows[e]], 1);
}

// single-kernel decoupled-lookback exclusive scan of g_cnt -> g_rp; zeroes g_cnt.
// Ticket ordering + all NB_SCAN blocks co-resident => forward progress guaranteed.
__global__ void scan_k() {
    __shared__ int sh[256];
    __shared__ int s_bid, s_pref;
    int t = threadIdx.x;
    if (t == 0) s_bid = atomicAdd(&g_ticket, 1);
    __syncthreads();
    int bid = s_bid;
    int i = bid * 256 + t;
    int c = (i < V_NODES) ? g_cnt[i] : 0;
    sh[t] = c;
    __syncthreads();
    for (int off = 1; off < 256; off <<= 1) {
        int v = sh[t];
        int a = (t >= off) ? sh[t - off] : 0;
        __syncthreads();
        sh[t] = v + a;
        __syncthreads();
    }
    int agg = sh[255];
    if (t == 0) {
        g_aggv[bid] = agg;
        __threadfence();
        atomicExch(&g_state[bid], 1);
        int running = 0;
        for (int j = bid - 1; j >= 0; j--) {
            int st;
            do { st = atomicAdd(&g_state[j], 0); } while (st == 0);
            if (st == 2) { running += atomicAdd(&g_inclv[j], 0); break; }
            running += atomicAdd(&g_aggv[j], 0);
        }
        g_inclv[bid] = running + agg;
        __threadfence();
        atomicExch(&g_state[bid], 2);
        s_pref = running;
        if (bid == NB_SCAN - 1) g_rp[V_NODES] = running + agg;
    }
    __syncthreads();
    int pref = s_pref;
    if (i < V_NODES) {
        g_rp[i] = pref + sh[t] - c;   // exclusive prefix
        g_cnt[i] = 0;                 // ready for scatter
    }
}

__global__ void scatter_k(const int* __restrict__ rows, const int* __restrict__ cols,
                          const float* __restrict__ vals, int E) {
    int e = blockIdx.x * blockDim.x + threadIdx.x;
    int stride = gridDim.x * blockDim.x;
    for (; e < E; e += stride) {
        int r = rows[e];
        int p = g_rp[r] + atomicAdd(&g_cnt[r], 1);
        g_ccol[p] = cols[e];
        g_cval[p] = vals[e];
    }
}

// ---------------- SpMM (fp16 in/out, fp32 accumulate) ----------------
// y[v, chunk*256 : +256] = sum_e val * x[col, slice].  One warp per (row, chunk):
// lane covers 8 features (uint4 = 16B); 32-edge coalesced prefetch + shuffle
// broadcast -> independent 512B gathers in flight.
__global__ void spmm_k(int yi, int xi) {
    int w = (blockIdx.x * blockDim.x + threadIdx.x) >> 5;
    if (w >= V_NODES) return;
    int lane = threadIdx.x & 31;

    const uint4* __restrict__ x4 = (const uint4*)pick_h(xi);
    uint4* __restrict__ y4 = (uint4*)pick_h(yi);
    int cbase = blockIdx.y * 32 + lane;   // uint4 offset within 64-uint4 row

    float acc[8];
#pragma unroll
    for (int q = 0; q < 8; q++) acc[q] = 0.f;

    int p0 = g_rp[w], p1 = g_rp[w + 1];
    for (int pb = p0; pb < p1; pb += 32) {
        int pc = pb + lane;
        int   c   = 0;
        float val = 0.f;
        if (pc < p1) { c = g_ccol[pc]; val = g_cval[pc]; }
        int n = p1 - pb; if (n > 32) n = 32;
#pragma unroll 4
        for (int j = 0; j < n; j++) {
            int   cj = __shfl_sync(0xffffffffu, c, j);
            float vj = __shfl_sync(0xffffffffu, val, j);
            uint4 raw = x4[(size_t)cj * 64 + cbase];
            const __half2* h2 = (const __half2*)&raw;
#pragma unroll
            for (int q = 0; q < 4; q++) {
                float2 f = __half22float2(h2[q]);
                acc[2 * q]     += vj * f.x;
                acc[2 * q + 1] += vj * f.y;
            }
        }
    }

    uint4 outv;
    __half2* oh = (__half2*)&outv;
#pragma unroll
    for (int q = 0; q < 4; q++) oh[q] = __floats2half2_rn(acc[2 * q], acc[2 * q + 1]);
    y4[(size_t)w * 64 + cbase] = outv;
}

// ---------------- split fp16-MMA GEMM ----------------
// part A (kb 0..16): acc = [P0..P3] @ W~[0..3], write fp32 partial to g_acc.
//   Runs concurrently with spmm4 (reads only P0..P3 + weights).
// part B (kb 16..20): acc = g_acc + P4 @ W~4, then transpose-epilogue + bias -> out.
// Identical arithmetic to the previous fused kernel (fp32 register partials pass
// through g_acc exactly).
#define HS       40                         // half stride (20 words: conflict-free)
#define A_ST     (128 * HS)                 // 5120 halfs = 10240 B
#define B_ST     (128 * HS)
#define STAGE_H  (A_ST + B_ST)              // 10240 halfs = 20480 B
#define GEMM_SMEM 67584                     // max(2*20480, epi 128*132*4)
#define EPI_STRIDE 132

__global__ __launch_bounds__(256, 2) void gemm_part_k(int kb0, int kb1, int final_part,
                                                      float* __restrict__ out,
                                                      const float* __restrict__ bias) {
    extern __shared__ __align__(16) __half shh[];
    int tid = threadIdx.x;
    int warp = tid >> 5, lane = tid & 31;
    int g = lane >> 2, tig = lane & 3;
    int wm = warp >> 1, wn = warp & 1;       // 4 x 2 warp grid
    int m_warp = wm * 32, n_warp = wn * 64;
    size_t row0 = (size_t)blockIdx.x * 128;

    float acc[2][8][4];
    if (final_part) {
        // resume from fp32 partial
#pragma unroll
        for (int mt = 0; mt < 2; mt++) {
#pragma unroll
            for (int nt = 0; nt < 8; nt++) {
                size_t r0 = row0 + m_warp + mt * 16 + g;
                size_t r1 = r0 + 8;
                int c = n_warp + nt * 8 + 2 * tig;
                float2 v01 = *(const float2*)(g_acc + r0 * 128 + c);
                float2 v23 = *(const float2*)(g_acc + r1 * 128 + c);
                acc[mt][nt][0] = v01.x; acc[mt][nt][1] = v01.y;
                acc[mt][nt][2] = v23.x; acc[mt][nt][3] = v23.y;
            }
        }
    } else {
#pragma unroll
        for (int mt = 0; mt < 2; mt++)
#pragma unroll
            for (int nt = 0; nt < 8; nt++)
#pragma unroll
                for (int j = 0; j < 4; j++) acc[mt][nt][j] = 0.f;
    }

    // ---- stage loader (cp.async): A 512 + B 512 chunks of 16B ----
    auto load_stage = [&](int s, int kb) {
        int kk  = kb >> 2;
        int ks0 = (kb & 3) * 32;
        const __half* A  = pick_h(kk);
        const __half* Wh = g_wh + kk * (CIN * COUT);
        __half* As = shh + s * STAGE_H;
        __half* Bh = As + A_ST;
#pragma unroll
        for (int q = 0; q < 2; q++) {
            int i = tid + 256 * q;           // A: 512 x 16B (row = 4 chunks of 8 halfs)
            int r = i >> 2, cg = i & 3;
            size_t ar = row0 + r;
            if (ar >= MROWS) ar = MROWS - 1;
            cp_async16(As + r * HS + cg * 8, A + ar * 128 + ks0 + cg * 8);
        }
#pragma unroll
        for (int q = 0; q < 2; q++) {
            int i = tid + 256 * q;           // B: 512 x 16B
            int r = i >> 2, cg = i & 3;
            cp_async16(Bh + r * HS + cg * 8, Wh + r * 128 + ks0 + cg * 8);
        }
        cp_commit();
    };

    load_stage(0, kb0);

    for (int kb = kb0; kb < kb1; kb++) {
        int s = (kb - kb0) & 1;
        if (kb < kb1 - 1) { load_stage(s ^ 1, kb + 1); cp_wait<1>(); }
        else              { cp_wait<0>(); }
        __syncthreads();

        const __half* Ar  = shh + s * STAGE_H;
        const __half* Bhr = Ar + A_ST;

#pragma unroll
        for (int kc = 0; kc < 2; kc++) {
            int k0 = kc * 16;
            uint32_t a[2][4];
#pragma unroll
            for (int mt = 0; mt < 2; mt++) {
                int rb = m_warp + mt * 16;
                a[mt][0] = *(const uint32_t*)(Ar + (rb + g)     * HS + k0 + 2 * tig);
                a[mt][1] = *(const uint32_t*)(Ar + (rb + g + 8) * HS + k0 + 2 * tig);
                a[mt][2] = *(const uint32_t*)(Ar + (rb + g)     * HS + k0 + 2 * tig + 8);
                a[mt][3] = *(const uint32_t*)(Ar + (rb + g + 8) * HS + k0 + 2 * tig + 8);
            }
#pragma unroll
            for (int nt = 0; nt < 8; nt++) {
                int nb = n_warp + nt * 8;
                uint32_t bh[2];
                bh[0] = *(const uint32_t*)(Bhr + (nb + g) * HS + k0 + 2 * tig);
                bh[1] = *(const uint32_t*)(Bhr + (nb + g) * HS + k0 + 2 * tig + 8);
#pragma unroll
                for (int mt = 0; mt < 2; mt++)
                    mma_f16(acc[mt][nt], a[mt], bh);
            }
        }
        __syncthreads();   // stage s consumed; safe to refill next iteration
    }

    if (!final_part) {
        // write fp32 partial (g_acc padded, no masking needed)
#pragma unroll
        for (int mt = 0; mt < 2; mt++) {
#pragma unroll
            for (int nt = 0; nt < 8; nt++) {
                size_t r0 = row0 + m_warp + mt * 16 + g;
                size_t r1 = r0 + 8;
                int c = n_warp + nt * 8 + 2 * tig;
                *(float2*)(g_acc + r0 * 128 + c) = make_float2(acc[mt][nt][0], acc[mt][nt][1]);
                *(float2*)(g_acc + r1 * 128 + c) = make_float2(acc[mt][nt][2], acc[mt][nt][3]);
            }
        }
        return;
    }

    // ---- epilogue: transpose via smem, add bias, write out ----
    // epi[o][m'] with m' = v_local + 32*b  (v_local = m_local>>2, b = m_local&3)
    float* epi = (float*)shh;   // 128 x EPI_STRIDE floats = 67584 B
    __syncthreads();

#pragma unroll
    for (int mt = 0; mt < 2; mt++) {
#pragma unroll
        for (int nt = 0; nt < 8; nt++) {
#pragma unroll
            for (int j = 0; j < 4; j++) {
                int c = n_warp + nt * 8 + 2 * tig + (j & 1);
                int m_loc = m_warp + mt * 16 + g + 8 * (j >> 1);
                int mp = (m_loc >> 2) + 32 * (m_loc & 3);
                epi[c * EPI_STRIDE + mp] = acc[mt][nt][j];
            }
        }
    }
    __syncthreads();

    int v0 = (int)(row0 >> 2);   // block's first node
    for (int p = warp; p < 512; p += 8) {
        int b = p >> 7, o = p & 127;
        float bv = bias[o];
        int vg = v0 + lane;
        float val = epi[o * EPI_STRIDE + 32 * b + lane] + bv;
        if (vg < V_NODES)
            out[(size_t)(b * 128 + o) * V_NODES + vg] = val;
    }
}

// ---------------- launch ----------------
extern "C" void kernel_launch(void* const* d_in, const int* in_sizes, int n_in,
                              void* d_out, int out_size) {
    const float* x        = (const float*)d_in[0];
    const float* lap_vals = (const float*)d_in[1];
    const float* weight   = (const float*)d_in[2];
    const float* bias     = (const float*)d_in[3];
    const int*   rows     = (const int*)d_in[4];
    const int*   cols     = (const int*)d_in[5];
    int E = in_sizes[1];
    float* out = (float*)d_out;

    // one-time host-side plumbing (no device memory involved)
    static cudaStream_t s_aux = nullptr;
    static cudaEvent_t  ev_fork = nullptr, ev_join = nullptr, ev_fork2 = nullptr, ev_join2 = nullptr;
    if (!s_aux) {
        cudaStreamCreateWithFlags(&s_aux, cudaStreamNonBlocking);
        cudaEventCreateWithFlags(&ev_fork, cudaEventDisableTiming);
        cudaEventCreateWithFlags(&ev_join, cudaEventDisableTiming);
        cudaEventCreateWithFlags(&ev_fork2, cudaEventDisableTiming);
        cudaEventCreateWithFlags(&ev_join2, cudaEventDisableTiming);
        cudaFuncSetAttribute(gemm_part_k, cudaFuncAttributeMaxDynamicSharedMemorySize, GEMM_SMEM);
    }

    dim3 tb(32, 32);
    dim3 tg((V_NODES + 31) / 32, FEAT / 32);
    dim3 spgrid((V_NODES * 32 + 255) / 256, NCHUNK);
    int gemm_grid = (MROWS + 127) / 128;

    // fork 1: CSR build chain on s_aux, concurrent with transpose_in on stream 0
    cudaEventRecord(ev_fork, 0);
    cudaStreamWaitEvent(s_aux, ev_fork, 0);

    wcomb_k<<<NB_SCAN, 256, 0, s_aux>>>(weight);   // weights + zero cnt/scan state
    count_k<<<1024, 256, 0, s_aux>>>(rows, E);
    scan_k<<<NB_SCAN, 256, 0, s_aux>>>();          // decoupled-lookback, zeroes g_cnt
    scatter_k<<<1024, 256, 0, s_aux>>>(rows, cols, lap_vals, E);

    transpose_in<<<tg, tb>>>(x);                   // stream 0, overlapped

    cudaEventRecord(ev_join, s_aux);
    cudaStreamWaitEvent(0, ev_join, 0);

    // powers P1..P3
    spmm_k<<<spgrid, 256>>>(1, 0);   // P1 = L P0
    spmm_k<<<spgrid, 256>>>(2, 1);   // P2 = L P1
    spmm_k<<<spgrid, 256>>>(3, 2);   // P3 = L P2

    // fork 2: gemmA (kk=0..3, reads P0..P3) overlapped with spmm4 (writes P4)
    cudaEventRecord(ev_fork2, 0);
    cudaStreamWaitEvent(s_aux, ev_fork2, 0);

    gemm_part_k<<<gemm_grid, 256, GEMM_SMEM, s_aux>>>(0, 16, 0, nullptr, nullptr);
    spmm_k<<<spgrid, 256>>>(4, 3);   // P4 = L P3 (stream 0)

    cudaEventRecord(ev_join2, s_aux);
    cudaStreamWaitEvent(0, ev_join2, 0);

    // gemmB: kk=4 + epilogue (transpose + bias -> out)
    gemm_part_k<<<gemm_grid, 256, GEMM_SMEM>>>(16, 20, 1, out, bias);
}

// round 14
// speedup vs baseline: 1.1170x; 1.1170x over previous
#include <cuda_runtime.h>
#include <cuda_fp16.h>
#include <cstdint>

#define V_NODES 50000
#define FEAT    512          // B * Cin
#define CIN     128
#define COUT    128
#define BATCH   4
#define MROWS   (V_NODES * BATCH)   // 200000
#define MAXE    800000
#define KORD    5
#define NB_SCAN ((V_NODES + 255) / 256)   // 196

// ---------------- static device scratch (no allocations allowed) ----------------
__device__ __half g_h0[(size_t)V_NODES * FEAT];     // P0..P4 fp16
__device__ __half g_h1[(size_t)V_NODES * FEAT];
__device__ __half g_h2[(size_t)V_NODES * FEAT];
__device__ __half g_h3[(size_t)V_NODES * FEAT];
__device__ __half g_h4[(size_t)V_NODES * FEAT];
__device__ __half g_wh[KORD * CIN * COUT];          // combined weights fp16 (layout [k][o][i])
__device__ int    g_rp[V_NODES + 1];
__device__ int    g_cnt[V_NODES];
__device__ int    g_ccol[MAXE];
__device__ float  g_cval[MAXE];
// decoupled-lookback scan state (re-zeroed by wcomb_k every replay)
__device__ int    g_ticket;
__device__ int    g_state[NB_SCAN];   // 0 = none, 1 = aggregate ready, 2 = prefix ready
__device__ int    g_aggv[NB_SCAN];
__device__ int    g_inclv[NB_SCAN];

__device__ __forceinline__ __half* pick_h(int i) {
    switch (i) {
        case 0: return g_h0;
        case 1: return g_h1;
        case 2: return g_h2;
        case 3: return g_h3;
        default: return g_h4;
    }
}

// ---------------- fp16 mma ----------------
__device__ __forceinline__ void mma_f16(float* d, const uint32_t* a, const uint32_t* b) {
    asm volatile(
        "mma.sync.aligned.m16n8k16.row.col.f32.f16.f16.f32 "
        "{%0,%1,%2,%3}, {%4,%5,%6,%7}, {%8,%9}, {%0,%1,%2,%3};"
        : "+f"(d[0]), "+f"(d[1]), "+f"(d[2]), "+f"(d[3])
        : "r"(a[0]), "r"(a[1]), "r"(a[2]), "r"(a[3]), "r"(b[0]), "r"(b[1]));
}

// ---------------- cp.async helpers ----------------
__device__ __forceinline__ void cp_async16(void* smem_dst, const void* gmem_src) {
    uint32_t s = (uint32_t)__cvta_generic_to_shared(smem_dst);
    asm volatile("cp.async.cg.shared.global [%0], [%1], 16;" :: "r"(s), "l"(gmem_src));
}
__device__ __forceinline__ void cp_commit() {
    asm volatile("cp.async.commit_group;");
}
template <int N>
__device__ __forceinline__ void cp_wait() {
    asm volatile("cp.async.wait_group %0;" :: "n"(N));
}

// ---------------- transpose: x (512, V) -> g_h0 (V, 512) fp16 ----------------
__global__ void transpose_in(const float* __restrict__ x) {
    __shared__ float tile[32][33];
    int v = blockIdx.x * 32 + threadIdx.x;
    int f = blockIdx.y * 32 + threadIdx.y;
    if (v < V_NODES)
        tile[threadIdx.y][threadIdx.x] = x[(size_t)f * V_NODES + v];
    __syncthreads();
    int vo = blockIdx.x * 32 + threadIdx.y;
    int fo = blockIdx.y * 32 + threadIdx.x;
    if (vo < V_NODES)
        g_h0[(size_t)vo * FEAT + fo] = __float2half(tile[threadIdx.x][threadIdx.y]);
}

// ---------------- combined weights (fp16, [k][o][i]) + zero scan state + g_cnt ----
// T0..T4 = {P0, P1, 2P2-P0, 4P3-3P1, 8P4-8P2+P0};  out = sum_k Tk Wk = sum_j Pj W~j
__global__ void wcomb_k(const float* __restrict__ w) {
    int gid = blockIdx.x * 256 + threadIdx.x;
    if (gid < V_NODES) g_cnt[gid] = 0;
    if (gid < NB_SCAN) g_state[gid] = 0;
    if (gid == 0) g_ticket = 0;
    if (gid >= CIN * COUT) return;
    const int S = CIN * COUT;
    float w0 = w[gid], w1 = w[gid + S], w2 = w[gid + 2 * S], w3 = w[gid + 3 * S], w4 = w[gid + 4 * S];
    float wt[KORD];
    wt[0] = w0 - w2 + w4;
    wt[1] = w1 - 3.f * w3;
    wt[2] = 2.f * w2 - 8.f * w4;
    wt[3] = 4.f * w3;
    wt[4] = 8.f * w4;
    int iin = gid >> 7, o = gid & 127;
#pragma unroll
    for (int j = 0; j < KORD; j++)
        g_wh[j * S + o * 128 + iin] = __float2half(wt[j]);
}

// ---------------- CSR build ----------------
__global__ void count_k(const int* __restrict__ rows, int E) {
    int e = blockIdx.x * blockDim.x + threadIdx.x;
    int stride = gridDim.x * blockDim.x;
    for (; e < E; e += stride) atomicAdd(&g_cnt[rows[e]], 1);
}

// single-kernel decoupled-lookback exclusive scan of g_cnt -> g_rp; zeroes g_cnt.
// Ticket ordering + all NB_SCAN blocks co-resident => forward progress guaranteed.
__global__ void scan_k() {
    __shared__ int sh[256];
    __shared__ int s_bid, s_pref;
    int t = threadIdx.x;
    if (t == 0) s_bid = atomicAdd(&g_ticket, 1);
    __syncthreads();
    int bid = s_bid;
    int i = bid * 256 + t;
    int c = (i < V_NODES) ? g_cnt[i] : 0;
    sh[t] = c;
    __syncthreads();
    for (int off = 1; off < 256; off <<= 1) {
        int v = sh[t];
        int a = (t >= off) ? sh[t - off] : 0;
        __syncthreads();
        sh[t] = v + a;
        __syncthreads();
    }
    int agg = sh[255];
    if (t == 0) {
        g_aggv[bid] = agg;
        __threadfence();
        atomicExch(&g_state[bid], 1);
        int running = 0;
        for (int j = bid - 1; j >= 0; j--) {
            int st;
            do { st = atomicAdd(&g_state[j], 0); } while (st == 0);
            if (st == 2) { running += atomicAdd(&g_inclv[j], 0); break; }
            running += atomicAdd(&g_aggv[j], 0);
        }
        g_inclv[bid] = running + agg;
        __threadfence();
        atomicExch(&g_state[bid], 2);
        s_pref = running;
        if (bid == NB_SCAN - 1) g_rp[V_NODES] = running + agg;
    }
    __syncthreads();
    int pref = s_pref;
    if (i < V_NODES) {
        g_rp[i] = pref + sh[t] - c;   // exclusive prefix
        g_cnt[i] = 0;                 // ready for scatter
    }
}

__global__ void scatter_k(const int* __restrict__ rows, const int* __restrict__ cols,
                          const float* __restrict__ vals, int E) {
    int e = blockIdx.x * blockDim.x + threadIdx.x;
    int stride = gridDim.x * blockDim.x;
    for (; e < E; e += stride) {
        int r = rows[e];
        int p = g_rp[r] + atomicAdd(&g_cnt[r], 1);
        g_ccol[p] = cols[e];
        g_cval[p] = vals[e];
    }
}

// ---------------- SpMM (fp16 in/out, fp32 accumulate), full 512-feature row ----
// One warp per row. Each lane covers 16 features via two independent uint4 loads
// (lane and lane+32 of the 64-uint4 row): per edge 2 gathers in flight per lane,
// 32-edge coalesced meta prefetch + shuffle broadcast. Same bytes as chunked
// version, half the meta traffic and blocks, double the per-edge MLP.
__global__ void spmm_k(int yi, int xi) {
    int w = (blockIdx.x * blockDim.x + threadIdx.x) >> 5;
    if (w >= V_NODES) return;
    int lane = threadIdx.x & 31;

    const uint4* __restrict__ x4 = (const uint4*)pick_h(xi);
    uint4* __restrict__ y4 = (uint4*)pick_h(yi);

    float acc[16];
#pragma unroll
    for (int q = 0; q < 16; q++) acc[q] = 0.f;

    int p0 = g_rp[w], p1 = g_rp[w + 1];
    for (int pb = p0; pb < p1; pb += 32) {
        int pc = pb + lane;
        int   c   = 0;
        float val = 0.f;
        if (pc < p1) { c = g_ccol[pc]; val = g_cval[pc]; }
        int n = p1 - pb; if (n > 32) n = 32;
#pragma unroll 4
        for (int j = 0; j < n; j++) {
            int   cj = __shfl_sync(0xffffffffu, c, j);
            float vj = __shfl_sync(0xffffffffu, val, j);
            uint4 r0 = x4[(size_t)cj * 64 + lane];
            uint4 r1 = x4[(size_t)cj * 64 + 32 + lane];
            const __half2* h0 = (const __half2*)&r0;
            const __half2* h1 = (const __half2*)&r1;
#pragma unroll
            for (int q = 0; q < 4; q++) {
                float2 f0 = __half22float2(h0[q]);
                float2 f1 = __half22float2(h1[q]);
                acc[2 * q]         += vj * f0.x;
                acc[2 * q + 1]     += vj * f0.y;
                acc[8 + 2 * q]     += vj * f1.x;
                acc[8 + 2 * q + 1] += vj * f1.y;
            }
        }
    }

    uint4 o0, o1;
    __half2* q0 = (__half2*)&o0;
    __half2* q1 = (__half2*)&o1;
#pragma unroll
    for (int q = 0; q < 4; q++) {
        q0[q] = __floats2half2_rn(acc[2 * q],     acc[2 * q + 1]);
        q1[q] = __floats2half2_rn(acc[8 + 2 * q], acc[8 + 2 * q + 1]);
    }
    y4[(size_t)w * 64 + lane] = o0;
    y4[(size_t)w * 64 + 32 + lane] = o1;
}

// ---------------- fused fp16-MMA GEMM + epilogue: out = ([P0..P4] @ W~)^T + bias ----
// A fp16 (exact), W~ fp16. 32 MMAs/stage, cp.async double-buffered. (R12 config.)
#define HS       40                         // half stride (20 words: conflict-free)
#define A_ST     (128 * HS)                 // 5120 halfs = 10240 B
#define B_ST     (128 * HS)
#define STAGE_H  (A_ST + B_ST)              // 10240 halfs = 20480 B
#define GEMM_SMEM 67584                     // max(2*20480, epi 128*132*4)
#define EPI_STRIDE 132

__global__ __launch_bounds__(256, 2) void gemm3_k(float* __restrict__ out,
                                                  const float* __restrict__ bias) {
    extern __shared__ __align__(16) __half shh[];
    int tid = threadIdx.x;
    int warp = tid >> 5, lane = tid & 31;
    int g = lane >> 2, tig = lane & 3;
    int wm = warp >> 1, wn = warp & 1;       // 4 x 2 warp grid
    int m_warp = wm * 32, n_warp = wn * 64;
    size_t row0 = (size_t)blockIdx.x * 128;

    float acc[2][8][4];
#pragma unroll
    for (int mt = 0; mt < 2; mt++)
#pragma unroll
        for (int nt = 0; nt < 8; nt++)
#pragma unroll
            for (int j = 0; j < 4; j++) acc[mt][nt][j] = 0.f;

    // ---- stage loader (cp.async): A 512 + B 512 chunks of 16B ----
    auto load_stage = [&](int s, int kb) {
        int kk  = kb >> 2;
        int ks0 = (kb & 3) * 32;
        const __half* A  = pick_h(kk);
        const __half* Wh = g_wh + kk * (CIN * COUT);
        __half* As = shh + s * STAGE_H;
        __half* Bh = As + A_ST;
#pragma unroll
        for (int q = 0; q < 2; q++) {
            int i = tid + 256 * q;           // A: 512 x 16B (row = 4 chunks of 8 halfs)
            int r = i >> 2, cg = i & 3;
            size_t ar = row0 + r;
            if (ar >= MROWS) ar = MROWS - 1;
            cp_async16(As + r * HS + cg * 8, A + ar * 128 + ks0 + cg * 8);
        }
#pragma unroll
        for (int q = 0; q < 2; q++) {
            int i = tid + 256 * q;           // B: 512 x 16B
            int r = i >> 2, cg = i & 3;
            cp_async16(Bh + r * HS + cg * 8, Wh + r * 128 + ks0 + cg * 8);
        }
        cp_commit();
    };

    load_stage(0, 0);

    for (int kb = 0; kb < 20; kb++) {
        int s = kb & 1;
        if (kb < 19) { load_stage(s ^ 1, kb + 1); cp_wait<1>(); }
        else         { cp_wait<0>(); }
        __syncthreads();

        const __half* Ar  = shh + s * STAGE_H;
        const __half* Bhr = Ar + A_ST;

#pragma unroll
        for (int kc = 0; kc < 2; kc++) {
            int k0 = kc * 16;
            uint32_t a[2][4];
#pragma unroll
            for (int mt = 0; mt < 2; mt++) {
                int rb = m_warp + mt * 16;
                a[mt][0] = *(const uint32_t*)(Ar + (rb + g)     * HS + k0 + 2 * tig);
                a[mt][1] = *(const uint32_t*)(Ar + (rb + g + 8) * HS + k0 + 2 * tig);
                a[mt][2] = *(const uint32_t*)(Ar + (rb + g)     * HS + k0 + 2 * tig + 8);
                a[mt][3] = *(const uint32_t*)(Ar + (rb + g + 8) * HS + k0 + 2 * tig + 8);
            }
#pragma unroll
            for (int nt = 0; nt < 8; nt++) {
                int nb = n_warp + nt * 8;
                uint32_t bh[2];
                bh[0] = *(const uint32_t*)(Bhr + (nb + g) * HS + k0 + 2 * tig);
                bh[1] = *(const uint32_t*)(Bhr + (nb + g) * HS + k0 + 2 * tig + 8);
#pragma unroll
                for (int mt = 0; mt < 2; mt++)
                    mma_f16(acc[mt][nt], a[mt], bh);
            }
        }
        __syncthreads();   // stage s consumed; safe to refill next iteration
    }

    // ---- epilogue: transpose via smem, add bias, write out ----
    // epi[o][m'] with m' = v_local + 32*b  (v_local = m_local>>2, b = m_local&3)
    float* epi = (float*)shh;   // 128 x EPI_STRIDE floats = 67584 B
    __syncthreads();

#pragma unroll
    for (int mt = 0; mt < 2; mt++) {
#pragma unroll
        for (int nt = 0; nt < 8; nt++) {
#pragma unroll
            for (int j = 0; j < 4; j++) {
                int c = n_warp + nt * 8 + 2 * tig + (j & 1);
                int m_loc = m_warp + mt * 16 + g + 8 * (j >> 1);
                int mp = (m_loc >> 2) + 32 * (m_loc & 3);
                epi[c * EPI_STRIDE + mp] = acc[mt][nt][j];
            }
        }
    }
    __syncthreads();

    int v0 = (int)(row0 >> 2);   // block's first node
    for (int p = warp; p < 512; p += 8) {
        int b = p >> 7, o = p & 127;
        float bv = bias[o];
        int vg = v0 + lane;
        float val = epi[o * EPI_STRIDE + 32 * b + lane] + bv;
        if (vg < V_NODES)
            out[(size_t)(b * 128 + o) * V_NODES + vg] = val;
    }
}

// ---------------- launch ----------------
extern "C" void kernel_launch(void* const* d_in, const int* in_sizes, int n_in,
                              void* d_out, int out_size) {
    const float* x        = (const float*)d_in[0];
    const float* lap_vals = (const float*)d_in[1];
    const float* weight   = (const float*)d_in[2];
    const float* bias     = (const float*)d_in[3];
    const int*   rows     = (const int*)d_in[4];
    const int*   cols     = (const int*)d_in[5];
    int E = in_sizes[1];
    float* out = (float*)d_out;

    // one-time host-side plumbing (no device memory involved)
    static cudaStream_t s_aux = nullptr;
    static cudaEvent_t  ev_fork = nullptr, ev_join = nullptr;
    if (!s_aux) {
        cudaStreamCreateWithFlags(&s_aux, cudaStreamNonBlocking);
        cudaEventCreateWithFlags(&ev_fork, cudaEventDisableTiming);
        cudaEventCreateWithFlags(&ev_join, cudaEventDisableTiming);
        cudaFuncSetAttribute(gemm3_k, cudaFuncAttributeMaxDynamicSharedMemorySize, GEMM_SMEM);
    }

    dim3 tb(32, 32);
    dim3 tg((V_NODES + 31) / 32, FEAT / 32);
    int spgrid = (V_NODES * 32 + 255) / 256;   // 6250 blocks, full-row warps

    // fork: CSR build chain on s_aux, concurrent with transpose_in on stream 0
    cudaEventRecord(ev_fork, 0);
    cudaStreamWaitEvent(s_aux, ev_fork, 0);

    wcomb_k<<<NB_SCAN, 256, 0, s_aux>>>(weight);   // weights + zero cnt/scan state
    count_k<<<1024, 256, 0, s_aux>>>(rows, E);
    scan_k<<<NB_SCAN, 256, 0, s_aux>>>();          // decoupled-lookback, zeroes g_cnt
    scatter_k<<<1024, 256, 0, s_aux>>>(rows, cols, lap_vals, E);

    transpose_in<<<tg, tb>>>(x);                   // stream 0, overlapped

    cudaEventRecord(ev_join, s_aux);
    cudaStreamWaitEvent(0, ev_join, 0);

    // pure powers P1..P4 (fp16 storage, fp32 accumulate)
    spmm_k<<<spgrid, 256>>>(1, 0);   // P1 = L P0
    spmm_k<<<spgrid, 256>>>(2, 1);   // P2 = L P1
    spmm_k<<<spgrid, 256>>>(3, 2);   // P3 = L P2
    spmm_k<<<spgrid, 256>>>(4, 3);   // P4 = L P3

    // fused projection + transpose + bias
    gemm3_k<<<(MROWS + 127) / 128, 256, GEMM_SMEM>>>(out, bias);
}